// round 1
// baseline (speedup 1.0000x reference)
#include <cuda_runtime.h>
#include <math.h>

#define BB 2
#define TT 2048
#define CC 2048
#define HH 16
#define DD 128
#define NEGF -1000000000.0f

// Scratch (device globals: no allocation allowed in kernel_launch)
__device__ float g_qkv[(size_t)3 * BB * HH * TT * DD];  // [3][B][H][T][D], 96 MB
__device__ float g_att[(size_t)BB * TT * CC];           // [B][T][C], 33.5 MB
__device__ float g_cos[TT * 64];
__device__ float g_sin[TT * 64];

// ---------------------------------------------------------------------------
// RoPE cos/sin table: cos/sin(t * 10000^(-2d/128)) for d in [0,64)
// ---------------------------------------------------------------------------
__global__ void rope_table_kernel() {
    int t = blockIdx.x;
    int d = threadIdx.x;  // 0..63
    double inv = exp2(-((double)(2 * d) / 128.0) * log2(10000.0));
    float f = (float)t * (float)inv;   // matches numpy f32 pos*inv_freq
    g_cos[t * 64 + d] = cosf(f);
    g_sin[t * 64 + d] = sinf(f);
}

// ---------------------------------------------------------------------------
// NT GEMM: out[m,n] = sum_k A[m,k] * W[n,k]
// BM=BN=128, BK=16, 256 threads, 8x8 per thread.
// EPI==0: scatter into g_qkv [3][B][H][T][D] (A = x, W = Wqkv, N=6144)
// EPI==1: A is g_att, plain row-major store to out (W = Wout, N=2048)
// ---------------------------------------------------------------------------
template <int EPI>
__global__ void __launch_bounds__(256) gemm_nt(const float* __restrict__ A_in,
                                               const float* __restrict__ W,
                                               float* __restrict__ out,
                                               int M, int N, int K) {
    __shared__ float As[16][128];
    __shared__ float Bs[16][128];

    const float* A = (EPI == 1) ? (const float*)g_att : A_in;

    const int tid = threadIdx.x;
    const int ty = tid >> 4, tx = tid & 15;
    const int m0 = blockIdx.y * 128, n0 = blockIdx.x * 128;

    float acc[8][8];
#pragma unroll
    for (int i = 0; i < 8; i++)
#pragma unroll
        for (int j = 0; j < 8; j++) acc[i][j] = 0.f;

    for (int k0 = 0; k0 < K; k0 += 16) {
#pragma unroll
        for (int u = 0; u < 2; u++) {
            int v = tid + u * 256;
            int r = v >> 2, c4 = (v & 3) << 2;
            float4 a = *(const float4*)(A + (size_t)(m0 + r) * K + k0 + c4);
            As[c4 + 0][r] = a.x; As[c4 + 1][r] = a.y;
            As[c4 + 2][r] = a.z; As[c4 + 3][r] = a.w;
            float4 b = *(const float4*)(W + (size_t)(n0 + r) * K + k0 + c4);
            Bs[c4 + 0][r] = b.x; Bs[c4 + 1][r] = b.y;
            Bs[c4 + 2][r] = b.z; Bs[c4 + 3][r] = b.w;
        }
        __syncthreads();
#pragma unroll
        for (int kk = 0; kk < 16; kk++) {
            float a[8], bb[8];
            *(float4*)&a[0] = *(const float4*)&As[kk][8 * ty];
            *(float4*)&a[4] = *(const float4*)&As[kk][8 * ty + 4];
            *(float4*)&bb[0] = *(const float4*)&Bs[kk][8 * tx];
            *(float4*)&bb[4] = *(const float4*)&Bs[kk][8 * tx + 4];
#pragma unroll
            for (int i = 0; i < 8; i++)
#pragma unroll
                for (int j = 0; j < 8; j++) acc[i][j] += a[i] * bb[j];
        }
        __syncthreads();
    }

    if (EPI == 0) {
        const int which = n0 >> 11;          // 0=q,1=k,2=v
        const int hh = (n0 >> 7) & 15;       // head (BN == D == 128)
#pragma unroll
        for (int i = 0; i < 8; i++) {
            int m = m0 + 8 * ty + i;
            int b = m >> 11, t = m & 2047;
            float* dst = g_qkv +
                ((((size_t)which * BB + b) * HH + hh) * TT + t) * DD + 8 * tx;
            *(float4*)dst = make_float4(acc[i][0], acc[i][1], acc[i][2], acc[i][3]);
            *(float4*)(dst + 4) = make_float4(acc[i][4], acc[i][5], acc[i][6], acc[i][7]);
        }
    } else {
#pragma unroll
        for (int i = 0; i < 8; i++) {
            int m = m0 + 8 * ty + i;
            float* dst = out + (size_t)m * N + n0 + 8 * tx;
            *(float4*)dst = make_float4(acc[i][0], acc[i][1], acc[i][2], acc[i][3]);
            *(float4*)(dst + 4) = make_float4(acc[i][4], acc[i][5], acc[i][6], acc[i][7]);
        }
    }
}

// ---------------------------------------------------------------------------
// RoPE in place on q and k slabs (first 2*B*H slabs of g_qkv)
// ---------------------------------------------------------------------------
__global__ void rope_kernel() {
    int idx = blockIdx.x;        // [0, 2*B*H*T)
    int t = idx & (TT - 1);
    int s = idx >> 11;           // slab [0, 2*B*H)
    float* p = g_qkv + ((size_t)s * TT + t) * DD;
    int d = threadIdx.x;         // 64 threads
    float c = g_cos[t * 64 + d], sn = g_sin[t * 64 + d];
    float x1 = p[d], x2 = p[d + 64];
    p[d]      = x1 * c - x2 * sn;
    p[d + 64] = x2 * c + x1 * sn;
}

// ---------------------------------------------------------------------------
// Flash attention: 64 q-rows per block, loop over 64-key tiles (causal).
// 256 threads: (ty,tx) 16x16; S: 4x4/thread, O: 4 rows x 8 cols/thread.
// ALiBi + causal mask computed in-kernel.
// ---------------------------------------------------------------------------
#define PQ 129
#define PP 68
#define ATTN_SMEM ((3 * 64 * PQ + 64 * PP) * 4)

__global__ void __launch_bounds__(256) attn_kernel() {
    extern __shared__ float sm[];
    float* Qs = sm;
    float* Ks = sm + 64 * PQ;
    float* Vs = sm + 2 * 64 * PQ;
    float* Ps = sm + 3 * 64 * PQ;

    const int bh = blockIdx.y;
    const int b = bh >> 4;
    const int h = bh & 15;
    const int qt = (gridDim.x - 1) - blockIdx.x;  // heavy tiles first
    const int i0 = qt * 64;
    const float slope = (float)exp2(-0.5 * (double)(h + 1));
    const float scale = 0.08838834764831843f;     // 1/sqrt(128)

    const float* Qg = g_qkv + (size_t)bh * TT * DD;
    const float* Kg = g_qkv + ((size_t)(BB * HH) + bh) * TT * DD;
    const float* Vg = g_qkv + ((size_t)(2 * BB * HH) + bh) * TT * DD;

    const int tid = threadIdx.x;
    const int ty = tid >> 4, tx = tid & 15;

    // Load Q tile (64 x 128)
    for (int v = tid; v < 64 * 32; v += 256) {
        int r = v >> 5;
        int c4 = (v & 31) << 2;
        float4 q = *(const float4*)(Qg + (size_t)(i0 + r) * DD + c4);
        Qs[r * PQ + c4 + 0] = q.x; Qs[r * PQ + c4 + 1] = q.y;
        Qs[r * PQ + c4 + 2] = q.z; Qs[r * PQ + c4 + 3] = q.w;
    }

    float m_run[4], l_run[4], acc[4][8];
#pragma unroll
    for (int i = 0; i < 4; i++) {
        m_run[i] = -INFINITY;
        l_run[i] = 0.f;
#pragma unroll
        for (int c = 0; c < 8; c++) acc[i][c] = 0.f;
    }

    for (int kt = 0; kt <= qt; kt++) {
        const int j0 = kt * 64;
        __syncthreads();  // prior PV done (and Q load visible before 2nd sync)
        for (int v = tid; v < 64 * 32; v += 256) {
            int r = v >> 5;
            int c4 = (v & 31) << 2;
            float4 k4 = *(const float4*)(Kg + (size_t)(j0 + r) * DD + c4);
            Ks[r * PQ + c4 + 0] = k4.x; Ks[r * PQ + c4 + 1] = k4.y;
            Ks[r * PQ + c4 + 2] = k4.z; Ks[r * PQ + c4 + 3] = k4.w;
            float4 v4 = *(const float4*)(Vg + (size_t)(j0 + r) * DD + c4);
            Vs[r * PQ + c4 + 0] = v4.x; Vs[r * PQ + c4 + 1] = v4.y;
            Vs[r * PQ + c4 + 2] = v4.z; Vs[r * PQ + c4 + 3] = v4.w;
        }
        __syncthreads();

        // S = Q K^T (4x4 per thread over 64x64 tile)
        float s[4][4];
#pragma unroll
        for (int i = 0; i < 4; i++)
#pragma unroll
            for (int j = 0; j < 4; j++) s[i][j] = 0.f;
#pragma unroll 4
        for (int kk = 0; kk < 128; kk++) {
            float qa[4], kb[4];
#pragma unroll
            for (int i = 0; i < 4; i++) qa[i] = Qs[(4 * ty + i) * PQ + kk];
#pragma unroll
            for (int j = 0; j < 4; j++) kb[j] = Ks[(4 * tx + j) * PQ + kk];
#pragma unroll
            for (int i = 0; i < 4; i++)
#pragma unroll
                for (int j = 0; j < 4; j++) s[i][j] += qa[i] * kb[j];
        }

        // scale + ALiBi + causal mask, online softmax update
#pragma unroll
        for (int i = 0; i < 4; i++) {
            const int ii = i0 + 4 * ty + i;
            float sv[4];
            float mt = -INFINITY;
#pragma unroll
            for (int j = 0; j < 4; j++) {
                int jj = j0 + 4 * tx + j;
                float val = (jj <= ii)
                    ? (s[i][j] * scale + slope * (float)(jj - ii))
                    : NEGF;
                sv[j] = val;
                mt = fmaxf(mt, val);
            }
#pragma unroll
            for (int o = 8; o > 0; o >>= 1)
                mt = fmaxf(mt, __shfl_xor_sync(0xffffffffu, mt, o));
            float mnew = fmaxf(m_run[i], mt);
            float corr = expf(m_run[i] - mnew);
            float rsum = 0.f;
#pragma unroll
            for (int j = 0; j < 4; j++) {
                float p = expf(sv[j] - mnew);
                Ps[(4 * ty + i) * PP + 4 * tx + j] = p;
                rsum += p;
            }
#pragma unroll
            for (int o = 8; o > 0; o >>= 1)
                rsum += __shfl_xor_sync(0xffffffffu, rsum, o);
            l_run[i] = l_run[i] * corr + rsum;
            m_run[i] = mnew;
#pragma unroll
            for (int c = 0; c < 8; c++) acc[i][c] *= corr;
        }
        __syncthreads();

        // O += P @ V
#pragma unroll 2
        for (int j = 0; j < 64; j++) {
            float pv[4];
#pragma unroll
            for (int i = 0; i < 4; i++) pv[i] = Ps[(4 * ty + i) * PP + j];
            float vv[8];
#pragma unroll
            for (int c = 0; c < 8; c++) vv[c] = Vs[j * PQ + 8 * tx + c];
#pragma unroll
            for (int i = 0; i < 4; i++)
#pragma unroll
                for (int c = 0; c < 8; c++) acc[i][c] += pv[i] * vv[c];
        }
    }

    // Normalize and write to g_att [B][T][C] at column h*128
#pragma unroll
    for (int i = 0; i < 4; i++) {
        float inv = 1.f / l_run[i];
        int t = i0 + 4 * ty + i;
        float* dst = g_att + ((size_t)b * TT + t) * CC + h * DD + 8 * tx;
#pragma unroll
        for (int c = 0; c < 8; c++) dst[c] = acc[i][c] * inv;
    }
}

// ---------------------------------------------------------------------------
extern "C" void kernel_launch(void* const* d_in, const int* in_sizes, int n_in,
                              void* d_out, int out_size) {
    (void)in_sizes; (void)n_in; (void)out_size;
    const float* x    = (const float*)d_in[0];
    // d_in[1] attn_mask and d_in[2] alibi_bias are recomputed in-kernel
    const float* Wqkv = (const float*)d_in[3];
    const float* Wout = (const float*)d_in[4];
    float* out = (float*)d_out;

    rope_table_kernel<<<TT, 64>>>();

    dim3 g1(3 * CC / 128, BB * TT / 128);   // (48, 32)
    gemm_nt<0><<<g1, 256>>>(x, Wqkv, nullptr, BB * TT, 3 * CC, CC);

    rope_kernel<<<2 * BB * HH * TT, 64>>>();

    cudaFuncSetAttribute(attn_kernel,
                         cudaFuncAttributeMaxDynamicSharedMemorySize, ATTN_SMEM);
    dim3 g2(TT / 64, BB * HH);              // (32, 32)
    attn_kernel<<<g2, 256, ATTN_SMEM>>>();

    dim3 g3(CC / 128, BB * TT / 128);       // (16, 32)
    gemm_nt<1><<<g3, 256>>>(nullptr, Wout, out, BB * TT, CC, CC);
}

// round 2
// speedup vs baseline: 1.6803x; 1.6803x over previous
#include <cuda_runtime.h>
#include <math.h>
#include <stdint.h>

#define BB 2
#define TT 2048
#define CC 2048
#define HH 16
#define DD 128
#define NEGF -1000000000.0f

// Scratch (device globals: no allocation allowed in kernel_launch)
__device__ float g_qkv[(size_t)3 * BB * HH * TT * DD];  // [3][B][H][T][D]
__device__ float g_att[(size_t)BB * TT * CC];           // [B][T][C]
__device__ float g_cos[TT * 64];
__device__ float g_sin[TT * 64];

// ---------------------------------------------------------------------------
__global__ void rope_table_kernel() {
    int t = blockIdx.x;
    int d = threadIdx.x;  // 0..63
    double inv = exp2(-((double)(2 * d) / 128.0) * log2(10000.0));
    float f = (float)t * (float)inv;
    g_cos[t * 64 + d] = cosf(f);
    g_sin[t * 64 + d] = sinf(f);
}

// ---------------------------------------------------------------------------
// tf32 mma.sync GEMM (NT): out[m,n] = sum_k A[m,k] * W[n,k]
// BM=128, BN=128, BK=32, 2-stage cp.async pipeline, 256 threads.
// Warp layout: 4 (m) x 2 (n), each warp 32x64 via m16n8k8 frags (2 m x 8 n).
// EPI==0: scatter into g_qkv [3][B][H][T][D]; EPI==1: A = g_att, plain store.
// ---------------------------------------------------------------------------
#define GBK 32
#define STAGE_F (128 * GBK)  // floats per tile buffer

__device__ __forceinline__ void cp_async16(void* smem, const void* gmem) {
    uint32_t s = (uint32_t)__cvta_generic_to_shared(smem);
    asm volatile("cp.async.cg.shared.global [%0], [%1], 16;\n" :: "r"(s), "l"(gmem));
}
__device__ __forceinline__ uint32_t f2tf32(float x) {
    uint32_t r;
    asm volatile("cvt.rna.tf32.f32 %0, %1;\n" : "=r"(r) : "f"(x));
    return r;
}
__device__ __forceinline__ void mma_tf32(float4& d, const uint32_t a[4], const uint32_t b[2]) {
    asm volatile(
        "mma.sync.aligned.m16n8k8.row.col.f32.tf32.tf32.f32 "
        "{%0,%1,%2,%3}, {%4,%5,%6,%7}, {%8,%9}, {%0,%1,%2,%3};\n"
        : "+f"(d.x), "+f"(d.y), "+f"(d.z), "+f"(d.w)
        : "r"(a[0]), "r"(a[1]), "r"(a[2]), "r"(a[3]), "r"(b[0]), "r"(b[1]));
}
// XOR-swizzled smem offset for element (row, k), 32 floats/row, chunk-of-4 swizzle
__device__ __forceinline__ int sw_off(int row, int k) {
    return row * GBK + ((((k >> 2) ^ (row & 7)) << 2) | (k & 3));
}

template <int EPI>
__global__ void __launch_bounds__(256, 2) gemm_tf32(const float* __restrict__ A_in,
                                                    const float* __restrict__ W,
                                                    float* __restrict__ out,
                                                    int M, int N, int K) {
    __shared__ float As[2][STAGE_F];
    __shared__ float Bs[2][STAGE_F];

    const float* A = (EPI == 1) ? (const float*)g_att : A_in;

    const int tid = threadIdx.x;
    const int m0 = blockIdx.y * 128, n0 = blockIdx.x * 128;

    const int wid = tid >> 5;
    const int lane = tid & 31;
    const int wm = wid & 3;        // 0..3  -> m offset wm*32
    const int wn = wid >> 2;       // 0..1  -> n offset wn*64
    const int g = lane >> 2;       // 0..7
    const int c = lane & 3;        // 0..3

    // gmem load mapping: 4 x (row = t>>3, chunk = t&7)
    const int lr = tid >> 3;       // 0..31 (row base, step 32)
    const int lc4 = tid & 7;       // chunk 0..7

    float4 acc[2][8];
#pragma unroll
    for (int i = 0; i < 2; i++)
#pragma unroll
        for (int j = 0; j < 8; j++) acc[i][j] = make_float4(0.f, 0.f, 0.f, 0.f);

    const int NT = K / GBK;

    // prologue: stage 0
    {
#pragma unroll
        for (int i = 0; i < 4; i++) {
            int r = lr + i * 32;
            int sw = (lc4 ^ (r & 7)) << 2;
            cp_async16(&As[0][r * GBK + sw], A + (size_t)(m0 + r) * K + lc4 * 4);
            cp_async16(&Bs[0][r * GBK + sw], W + (size_t)(n0 + r) * K + lc4 * 4);
        }
        asm volatile("cp.async.commit_group;\n");
    }

    for (int kt = 0; kt < NT; kt++) {
        int cur = kt & 1;
        if (kt + 1 < NT) {
            int nxt = cur ^ 1;
            int k0 = (kt + 1) * GBK;
#pragma unroll
            for (int i = 0; i < 4; i++) {
                int r = lr + i * 32;
                int sw = (lc4 ^ (r & 7)) << 2;
                cp_async16(&As[nxt][r * GBK + sw], A + (size_t)(m0 + r) * K + k0 + lc4 * 4);
                cp_async16(&Bs[nxt][r * GBK + sw], W + (size_t)(n0 + r) * K + k0 + lc4 * 4);
            }
        }
        asm volatile("cp.async.commit_group;\n");
        asm volatile("cp.async.wait_group 1;\n");
        __syncthreads();

        const float* as = As[cur];
        const float* bs = Bs[cur];
#pragma unroll
        for (int ks = 0; ks < 4; ks++) {
            const int k0 = ks * 8;
            uint32_t ua[2][4], ub[8][2];
#pragma unroll
            for (int mf = 0; mf < 2; mf++) {
                int r0 = wm * 32 + mf * 16 + g;
                ua[mf][0] = f2tf32(as[sw_off(r0,     k0 + c)]);
                ua[mf][1] = f2tf32(as[sw_off(r0 + 8, k0 + c)]);
                ua[mf][2] = f2tf32(as[sw_off(r0,     k0 + c + 4)]);
                ua[mf][3] = f2tf32(as[sw_off(r0 + 8, k0 + c + 4)]);
            }
#pragma unroll
            for (int nf = 0; nf < 8; nf++) {
                int n = wn * 64 + nf * 8 + g;
                ub[nf][0] = f2tf32(bs[sw_off(n, k0 + c)]);
                ub[nf][1] = f2tf32(bs[sw_off(n, k0 + c + 4)]);
            }
#pragma unroll
            for (int mf = 0; mf < 2; mf++)
#pragma unroll
                for (int nf = 0; nf < 8; nf++) mma_tf32(acc[mf][nf], ua[mf], ub[nf]);
        }
        __syncthreads();
    }

    // epilogue: acc element (mf,nf): rows wm*32+mf*16+{g,g+8}, cols wn*64+nf*8+{2c,2c+1}
    if (EPI == 0) {
        const int which = n0 >> 11;
        const int hh = (n0 >> 7) & 15;
#pragma unroll
        for (int mf = 0; mf < 2; mf++) {
            int r0 = m0 + wm * 32 + mf * 16 + g;
            int b0i = r0 >> 11, t0 = r0 & 2047;
            int r1 = r0 + 8;
            int b1i = r1 >> 11, t1 = r1 & 2047;
            float* base0 = g_qkv + ((((size_t)which * BB + b0i) * HH + hh) * TT + t0) * DD;
            float* base1 = g_qkv + ((((size_t)which * BB + b1i) * HH + hh) * TT + t1) * DD;
#pragma unroll
            for (int nf = 0; nf < 8; nf++) {
                int col = wn * 64 + nf * 8 + 2 * c;
                *(float2*)(base0 + col) = make_float2(acc[mf][nf].x, acc[mf][nf].y);
                *(float2*)(base1 + col) = make_float2(acc[mf][nf].z, acc[mf][nf].w);
            }
        }
    } else {
#pragma unroll
        for (int mf = 0; mf < 2; mf++) {
            int r0 = m0 + wm * 32 + mf * 16 + g;
            int r1 = r0 + 8;
#pragma unroll
            for (int nf = 0; nf < 8; nf++) {
                int col = n0 + wn * 64 + nf * 8 + 2 * c;
                *(float2*)(out + (size_t)r0 * N + col) = make_float2(acc[mf][nf].x, acc[mf][nf].y);
                *(float2*)(out + (size_t)r1 * N + col) = make_float2(acc[mf][nf].z, acc[mf][nf].w);
            }
        }
    }
}

// ---------------------------------------------------------------------------
// RoPE in place on q and k slabs
// ---------------------------------------------------------------------------
__global__ void rope_kernel() {
    int idx = blockIdx.x;
    int t = idx & (TT - 1);
    int s = idx >> 11;
    float* p = g_qkv + ((size_t)s * TT + t) * DD;
    int d = threadIdx.x;  // 64
    float cs = g_cos[t * 64 + d], sn = g_sin[t * 64 + d];
    float x1 = p[d], x2 = p[d + 64];
    p[d]      = x1 * cs - x2 * sn;
    p[d + 64] = x2 * cs + x1 * sn;
}

// ---------------------------------------------------------------------------
// Flash attention (SIMT, unchanged from R1)
// ---------------------------------------------------------------------------
#define PQ 129
#define PP 68
#define ATTN_SMEM ((3 * 64 * PQ + 64 * PP) * 4)

__global__ void __launch_bounds__(256) attn_kernel() {
    extern __shared__ float sm[];
    float* Qs = sm;
    float* Ks = sm + 64 * PQ;
    float* Vs = sm + 2 * 64 * PQ;
    float* Ps = sm + 3 * 64 * PQ;

    const int bh = blockIdx.y;
    const int b = bh >> 4;
    const int h = bh & 15;
    const int qt = (gridDim.x - 1) - blockIdx.x;
    const int i0 = qt * 64;
    const float slope = (float)exp2(-0.5 * (double)(h + 1));
    const float scale = 0.08838834764831843f;

    const float* Qg = g_qkv + (size_t)bh * TT * DD;
    const float* Kg = g_qkv + ((size_t)(BB * HH) + bh) * TT * DD;
    const float* Vg = g_qkv + ((size_t)(2 * BB * HH) + bh) * TT * DD;

    const int tid = threadIdx.x;
    const int ty = tid >> 4, tx = tid & 15;

    for (int v = tid; v < 64 * 32; v += 256) {
        int r = v >> 5;
        int c4 = (v & 31) << 2;
        float4 q = *(const float4*)(Qg + (size_t)(i0 + r) * DD + c4);
        Qs[r * PQ + c4 + 0] = q.x; Qs[r * PQ + c4 + 1] = q.y;
        Qs[r * PQ + c4 + 2] = q.z; Qs[r * PQ + c4 + 3] = q.w;
    }

    float m_run[4], l_run[4], acc[4][8];
#pragma unroll
    for (int i = 0; i < 4; i++) {
        m_run[i] = -INFINITY;
        l_run[i] = 0.f;
#pragma unroll
        for (int cc2 = 0; cc2 < 8; cc2++) acc[i][cc2] = 0.f;
    }

    for (int kt = 0; kt <= qt; kt++) {
        const int j0 = kt * 64;
        __syncthreads();
        for (int v = tid; v < 64 * 32; v += 256) {
            int r = v >> 5;
            int c4 = (v & 31) << 2;
            float4 k4 = *(const float4*)(Kg + (size_t)(j0 + r) * DD + c4);
            Ks[r * PQ + c4 + 0] = k4.x; Ks[r * PQ + c4 + 1] = k4.y;
            Ks[r * PQ + c4 + 2] = k4.z; Ks[r * PQ + c4 + 3] = k4.w;
            float4 v4 = *(const float4*)(Vg + (size_t)(j0 + r) * DD + c4);
            Vs[r * PQ + c4 + 0] = v4.x; Vs[r * PQ + c4 + 1] = v4.y;
            Vs[r * PQ + c4 + 2] = v4.z; Vs[r * PQ + c4 + 3] = v4.w;
        }
        __syncthreads();

        float s[4][4];
#pragma unroll
        for (int i = 0; i < 4; i++)
#pragma unroll
            for (int j = 0; j < 4; j++) s[i][j] = 0.f;
#pragma unroll 4
        for (int kk = 0; kk < 128; kk++) {
            float qa[4], kb[4];
#pragma unroll
            for (int i = 0; i < 4; i++) qa[i] = Qs[(4 * ty + i) * PQ + kk];
#pragma unroll
            for (int j = 0; j < 4; j++) kb[j] = Ks[(4 * tx + j) * PQ + kk];
#pragma unroll
            for (int i = 0; i < 4; i++)
#pragma unroll
                for (int j = 0; j < 4; j++) s[i][j] += qa[i] * kb[j];
        }

#pragma unroll
        for (int i = 0; i < 4; i++) {
            const int ii = i0 + 4 * ty + i;
            float sv[4];
            float mt = -INFINITY;
#pragma unroll
            for (int j = 0; j < 4; j++) {
                int jj = j0 + 4 * tx + j;
                float val = (jj <= ii)
                    ? (s[i][j] * scale + slope * (float)(jj - ii))
                    : NEGF;
                sv[j] = val;
                mt = fmaxf(mt, val);
            }
#pragma unroll
            for (int o = 8; o > 0; o >>= 1)
                mt = fmaxf(mt, __shfl_xor_sync(0xffffffffu, mt, o));
            float mnew = fmaxf(m_run[i], mt);
            float corr = expf(m_run[i] - mnew);
            float rsum = 0.f;
#pragma unroll
            for (int j = 0; j < 4; j++) {
                float p = expf(sv[j] - mnew);
                Ps[(4 * ty + i) * PP + 4 * tx + j] = p;
                rsum += p;
            }
#pragma unroll
            for (int o = 8; o > 0; o >>= 1)
                rsum += __shfl_xor_sync(0xffffffffu, rsum, o);
            l_run[i] = l_run[i] * corr + rsum;
            m_run[i] = mnew;
#pragma unroll
            for (int cc2 = 0; cc2 < 8; cc2++) acc[i][cc2] *= corr;
        }
        __syncthreads();

#pragma unroll 2
        for (int j = 0; j < 64; j++) {
            float pv[4];
#pragma unroll
            for (int i = 0; i < 4; i++) pv[i] = Ps[(4 * ty + i) * PP + j];
            float vv[8];
#pragma unroll
            for (int cc2 = 0; cc2 < 8; cc2++) vv[cc2] = Vs[j * PQ + 8 * tx + cc2];
#pragma unroll
            for (int i = 0; i < 4; i++)
#pragma unroll
                for (int cc2 = 0; cc2 < 8; cc2++) acc[i][cc2] += pv[i] * vv[cc2];
        }
    }

#pragma unroll
    for (int i = 0; i < 4; i++) {
        float inv = 1.f / l_run[i];
        int t = i0 + 4 * ty + i;
        float* dst = g_att + ((size_t)b * TT + t) * CC + h * DD + 8 * tx;
#pragma unroll
        for (int cc2 = 0; cc2 < 8; cc2++) dst[cc2] = acc[i][cc2] * inv;
    }
}

// ---------------------------------------------------------------------------
extern "C" void kernel_launch(void* const* d_in, const int* in_sizes, int n_in,
                              void* d_out, int out_size) {
    (void)in_sizes; (void)n_in; (void)out_size;
    const float* x    = (const float*)d_in[0];
    const float* Wqkv = (const float*)d_in[3];
    const float* Wout = (const float*)d_in[4];
    float* out = (float*)d_out;

    rope_table_kernel<<<TT, 64>>>();

    dim3 g1(3 * CC / 128, BB * TT / 128);   // (48, 32)
    gemm_tf32<0><<<g1, 256>>>(x, Wqkv, nullptr, BB * TT, 3 * CC, CC);

    rope_kernel<<<2 * BB * HH * TT, 64>>>();

    cudaFuncSetAttribute(attn_kernel,
                         cudaFuncAttributeMaxDynamicSharedMemorySize, ATTN_SMEM);
    dim3 g2(TT / 64, BB * HH);              // (32, 32)
    attn_kernel<<<g2, 256, ATTN_SMEM>>>();

    dim3 g3(CC / 128, BB * TT / 128);       // (16, 32)
    gemm_tf32<1><<<g3, 256>>>(nullptr, Wout, out, BB * TT, CC, CC);
}

// round 3
// speedup vs baseline: 2.6185x; 1.5584x over previous
#include <cuda_runtime.h>
#include <math.h>
#include <stdint.h>

#define BB 2
#define TT 2048
#define CC 2048
#define HH 16
#define DD 128
#define NEGF -1000000000.0f

// Scratch (device globals: no allocation allowed in kernel_launch)
__device__ float g_qkv[(size_t)3 * BB * HH * TT * DD];  // [3][B][H][T][D]
__device__ float g_att[(size_t)BB * TT * CC];           // [B][T][C]
__device__ float g_cos[TT * 64];
__device__ float g_sin[TT * 64];

// ---------------------------------------------------------------------------
__global__ void rope_table_kernel() {
    int t = blockIdx.x;
    int d = threadIdx.x;  // 0..63
    double inv = exp2(-((double)(2 * d) / 128.0) * log2(10000.0));
    float f = (float)t * (float)inv;
    g_cos[t * 64 + d] = cosf(f);
    g_sin[t * 64 + d] = sinf(f);
}

// ---------------------------------------------------------------------------
// mma helpers
// ---------------------------------------------------------------------------
__device__ __forceinline__ void cp_async16(void* smem, const void* gmem) {
    uint32_t s = (uint32_t)__cvta_generic_to_shared(smem);
    asm volatile("cp.async.cg.shared.global [%0], [%1], 16;\n" :: "r"(s), "l"(gmem));
}
__device__ __forceinline__ uint32_t f2tf32(float x) {
    uint32_t r;
    asm volatile("cvt.rna.tf32.f32 %0, %1;\n" : "=r"(r) : "f"(x));
    return r;
}
__device__ __forceinline__ void split2(float x, uint32_t& hi, uint32_t& lo) {
    hi = f2tf32(x);
    lo = f2tf32(x - __uint_as_float(hi));
}
__device__ __forceinline__ void mma_tf32(float4& d, const uint32_t a[4], const uint32_t b[2]) {
    asm volatile(
        "mma.sync.aligned.m16n8k8.row.col.f32.tf32.tf32.f32 "
        "{%0,%1,%2,%3}, {%4,%5,%6,%7}, {%8,%9}, {%0,%1,%2,%3};\n"
        : "+f"(d.x), "+f"(d.y), "+f"(d.z), "+f"(d.w)
        : "r"(a[0]), "r"(a[1]), "r"(a[2]), "r"(a[3]), "r"(b[0]), "r"(b[1]));
}

// ---------------------------------------------------------------------------
// tf32 mma.sync GEMM (NT), unchanged from R2
// ---------------------------------------------------------------------------
#define GBK 32
#define STAGE_F (128 * GBK)

__device__ __forceinline__ int sw_off(int row, int k) {
    return row * GBK + ((((k >> 2) ^ (row & 7)) << 2) | (k & 3));
}

template <int EPI>
__global__ void __launch_bounds__(256, 2) gemm_tf32(const float* __restrict__ A_in,
                                                    const float* __restrict__ W,
                                                    float* __restrict__ out,
                                                    int M, int N, int K) {
    __shared__ float As[2][STAGE_F];
    __shared__ float Bs[2][STAGE_F];

    const float* A = (EPI == 1) ? (const float*)g_att : A_in;

    const int tid = threadIdx.x;
    const int m0 = blockIdx.y * 128, n0 = blockIdx.x * 128;

    const int wid = tid >> 5;
    const int lane = tid & 31;
    const int wm = wid & 3;
    const int wn = wid >> 2;
    const int g = lane >> 2;
    const int c = lane & 3;

    const int lr = tid >> 3;
    const int lc4 = tid & 7;

    float4 acc[2][8];
#pragma unroll
    for (int i = 0; i < 2; i++)
#pragma unroll
        for (int j = 0; j < 8; j++) acc[i][j] = make_float4(0.f, 0.f, 0.f, 0.f);

    const int NT = K / GBK;

    {
#pragma unroll
        for (int i = 0; i < 4; i++) {
            int r = lr + i * 32;
            int sw = (lc4 ^ (r & 7)) << 2;
            cp_async16(&As[0][r * GBK + sw], A + (size_t)(m0 + r) * K + lc4 * 4);
            cp_async16(&Bs[0][r * GBK + sw], W + (size_t)(n0 + r) * K + lc4 * 4);
        }
        asm volatile("cp.async.commit_group;\n");
    }

    for (int kt = 0; kt < NT; kt++) {
        int cur = kt & 1;
        if (kt + 1 < NT) {
            int nxt = cur ^ 1;
            int k0 = (kt + 1) * GBK;
#pragma unroll
            for (int i = 0; i < 4; i++) {
                int r = lr + i * 32;
                int sw = (lc4 ^ (r & 7)) << 2;
                cp_async16(&As[nxt][r * GBK + sw], A + (size_t)(m0 + r) * K + k0 + lc4 * 4);
                cp_async16(&Bs[nxt][r * GBK + sw], W + (size_t)(n0 + r) * K + k0 + lc4 * 4);
            }
        }
        asm volatile("cp.async.commit_group;\n");
        asm volatile("cp.async.wait_group 1;\n");
        __syncthreads();

        const float* as = As[cur];
        const float* bs = Bs[cur];
#pragma unroll
        for (int ks = 0; ks < 4; ks++) {
            const int k0 = ks * 8;
            uint32_t ua[2][4], ub[8][2];
#pragma unroll
            for (int mf = 0; mf < 2; mf++) {
                int r0 = wm * 32 + mf * 16 + g;
                ua[mf][0] = f2tf32(as[sw_off(r0,     k0 + c)]);
                ua[mf][1] = f2tf32(as[sw_off(r0 + 8, k0 + c)]);
                ua[mf][2] = f2tf32(as[sw_off(r0,     k0 + c + 4)]);
                ua[mf][3] = f2tf32(as[sw_off(r0 + 8, k0 + c + 4)]);
            }
#pragma unroll
            for (int nf = 0; nf < 8; nf++) {
                int n = wn * 64 + nf * 8 + g;
                ub[nf][0] = f2tf32(bs[sw_off(n, k0 + c)]);
                ub[nf][1] = f2tf32(bs[sw_off(n, k0 + c + 4)]);
            }
#pragma unroll
            for (int mf = 0; mf < 2; mf++)
#pragma unroll
                for (int nf = 0; nf < 8; nf++) mma_tf32(acc[mf][nf], ua[mf], ub[nf]);
        }
        __syncthreads();
    }

    if (EPI == 0) {
        const int which = n0 >> 11;
        const int hh = (n0 >> 7) & 15;
#pragma unroll
        for (int mf = 0; mf < 2; mf++) {
            int r0 = m0 + wm * 32 + mf * 16 + g;
            int b0i = r0 >> 11, t0 = r0 & 2047;
            int r1 = r0 + 8;
            int b1i = r1 >> 11, t1 = r1 & 2047;
            float* base0 = g_qkv + ((((size_t)which * BB + b0i) * HH + hh) * TT + t0) * DD;
            float* base1 = g_qkv + ((((size_t)which * BB + b1i) * HH + hh) * TT + t1) * DD;
#pragma unroll
            for (int nf = 0; nf < 8; nf++) {
                int col = wn * 64 + nf * 8 + 2 * c;
                *(float2*)(base0 + col) = make_float2(acc[mf][nf].x, acc[mf][nf].y);
                *(float2*)(base1 + col) = make_float2(acc[mf][nf].z, acc[mf][nf].w);
            }
        }
    } else {
#pragma unroll
        for (int mf = 0; mf < 2; mf++) {
            int r0 = m0 + wm * 32 + mf * 16 + g;
            int r1 = r0 + 8;
#pragma unroll
            for (int nf = 0; nf < 8; nf++) {
                int col = n0 + wn * 64 + nf * 8 + 2 * c;
                *(float2*)(out + (size_t)r0 * N + col) = make_float2(acc[mf][nf].x, acc[mf][nf].y);
                *(float2*)(out + (size_t)r1 * N + col) = make_float2(acc[mf][nf].z, acc[mf][nf].w);
            }
        }
    }
}

// ---------------------------------------------------------------------------
// RoPE in place on q and k slabs
// ---------------------------------------------------------------------------
__global__ void rope_kernel() {
    int idx = blockIdx.x;
    int t = idx & (TT - 1);
    int s = idx >> 11;
    float* p = g_qkv + ((size_t)s * TT + t) * DD;
    int d = threadIdx.x;  // 64
    float cs = g_cos[t * 64 + d], sn = g_sin[t * 64 + d];
    float x1 = p[d], x2 = p[d + 64];
    p[d]      = x1 * cs - x2 * sn;
    p[d + 64] = x2 * cs + x1 * sn;
}

// ---------------------------------------------------------------------------
// Flash attention on tensor cores.
// BM=128 q rows per CTA, BN=64 keys per iteration, 8 warps (16 rows each).
// S = QK^T with 3xTF32; PV with 2xTF32 (P split, V hi-only).
// Smem: Q fp32 [128x132], Khi/Klo tf32 [64x132], Vhi tf32 [64x136], P fp32 [128x68]
// ---------------------------------------------------------------------------
#define AM 128
#define AN 64
#define QST 132
#define KST 132
#define VST 136
#define PST 68

#define OFF_Q   0
#define OFF_KHI (AM * QST)                  // 16896
#define OFF_KLO (OFF_KHI + AN * KST)        // +8448
#define OFF_VHI (OFF_KLO + AN * KST)        // +8448
#define OFF_P   (OFF_VHI + AN * VST)        // +8704
#define ATTN_F  (OFF_P + AM * PST)          // +8704 = 51200 floats
#define ATTN_SMEM (ATTN_F * 4)              // 204800 B

__global__ void __launch_bounds__(256) attn_mma_kernel() {
    extern __shared__ float sm[];
    float* Qs  = sm + OFF_Q;
    float* Khi = sm + OFF_KHI;
    float* Klo = sm + OFF_KLO;
    float* Vhi = sm + OFF_VHI;
    float* Ps  = sm + OFF_P;
    const uint32_t* uKhi = (const uint32_t*)Khi;
    const uint32_t* uKlo = (const uint32_t*)Klo;
    const uint32_t* uVhi = (const uint32_t*)Vhi;

    const int bh = blockIdx.y;
    const int b = bh >> 4;
    const int h = bh & 15;
    const int qt = (gridDim.x - 1) - blockIdx.x;   // heavy tiles first
    const int i0 = qt * AM;
    const float slope = (float)exp2(-0.5 * (double)(h + 1));
    const float scale = 0.08838834764831843f;      // 1/sqrt(128)

    const float* Qg = g_qkv + (size_t)bh * TT * DD;
    const float* Kg = g_qkv + ((size_t)(BB * HH) + bh) * TT * DD;
    const float* Vg = g_qkv + ((size_t)(2 * BB * HH) + bh) * TT * DD;

    const int tid = threadIdx.x;
    const int w = tid >> 5, lane = tid & 31;
    const int g = lane >> 2, c = lane & 3;
    const int r0 = w * 16;          // warp's row block within tile

    // Load Q tile 128x128 fp32
    for (int v = tid; v < AM * 32; v += 256) {
        int r = v >> 5, c4 = (v & 31) << 2;
        float4 q = *(const float4*)(Qg + (size_t)(i0 + r) * DD + c4);
        float* d = Qs + r * QST + c4;
        d[0] = q.x; d[1] = q.y; d[2] = q.z; d[3] = q.w;
    }

    float4 o[16];
#pragma unroll
    for (int i = 0; i < 16; i++) o[i] = make_float4(0.f, 0.f, 0.f, 0.f);
    float mr0 = -INFINITY, mr1 = -INFINITY, lr0 = 0.f, lr1 = 0.f;

    const int ntiles = 2 * (qt + 1);
    for (int kt = 0; kt < ntiles; kt++) {
        const int j0 = kt * AN;
        __syncthreads();  // previous iteration's PV / Q-load done

        // Load + split K tile, load V tile (hi)
        for (int v = tid; v < AN * 32; v += 256) {
            int r = v >> 5, c4 = (v & 31) << 2;
            float4 k4 = *(const float4*)(Kg + (size_t)(j0 + r) * DD + c4);
            float4 v4 = *(const float4*)(Vg + (size_t)(j0 + r) * DD + c4);
            uint4 khi, klo, vhi;
            split2(k4.x, khi.x, klo.x);
            split2(k4.y, khi.y, klo.y);
            split2(k4.z, khi.z, klo.z);
            split2(k4.w, khi.w, klo.w);
            vhi.x = f2tf32(v4.x); vhi.y = f2tf32(v4.y);
            vhi.z = f2tf32(v4.z); vhi.w = f2tf32(v4.w);
            *(uint4*)(Khi + r * KST + c4) = khi;
            *(uint4*)(Klo + r * KST + c4) = klo;
            *(uint4*)(Vhi + r * VST + c4) = vhi;
        }
        __syncthreads();

        // ---- S = Q K^T (16 x 64 per warp), 3xTF32 ----
        float4 s[8];
#pragma unroll
        for (int nf = 0; nf < 8; nf++) s[nf] = make_float4(0.f, 0.f, 0.f, 0.f);
#pragma unroll 4
        for (int kc = 0; kc < 16; kc++) {
            const int k0 = kc * 8;
            uint32_t ahi[4], alo[4];
            split2(Qs[(r0 + g)     * QST + k0 + c],     ahi[0], alo[0]);
            split2(Qs[(r0 + g + 8) * QST + k0 + c],     ahi[1], alo[1]);
            split2(Qs[(r0 + g)     * QST + k0 + c + 4], ahi[2], alo[2]);
            split2(Qs[(r0 + g + 8) * QST + k0 + c + 4], ahi[3], alo[3]);
#pragma unroll
            for (int nf = 0; nf < 8; nf++) {
                uint32_t bhi[2], blo[2];
                int nb = (nf * 8 + g) * KST + k0;
                bhi[0] = uKhi[nb + c]; bhi[1] = uKhi[nb + c + 4];
                blo[0] = uKlo[nb + c]; blo[1] = uKlo[nb + c + 4];
                mma_tf32(s[nf], ahi, bhi);
                mma_tf32(s[nf], ahi, blo);
                mma_tf32(s[nf], alo, bhi);
            }
        }

        // ---- softmax (warp-local) ----
        const int ig0 = i0 + r0 + g;
        const int ig1 = ig0 + 8;
        float tm0 = -INFINITY, tm1 = -INFINITY;
#pragma unroll
        for (int nf = 0; nf < 8; nf++) {
            int jb = j0 + nf * 8 + 2 * c;
            s[nf].x = (jb     <= ig0) ? fmaf(slope, (float)(jb     - ig0), s[nf].x * scale) : NEGF;
            s[nf].y = (jb + 1 <= ig0) ? fmaf(slope, (float)(jb + 1 - ig0), s[nf].y * scale) : NEGF;
            s[nf].z = (jb     <= ig1) ? fmaf(slope, (float)(jb     - ig1), s[nf].z * scale) : NEGF;
            s[nf].w = (jb + 1 <= ig1) ? fmaf(slope, (float)(jb + 1 - ig1), s[nf].w * scale) : NEGF;
            tm0 = fmaxf(tm0, fmaxf(s[nf].x, s[nf].y));
            tm1 = fmaxf(tm1, fmaxf(s[nf].z, s[nf].w));
        }
        tm0 = fmaxf(tm0, __shfl_xor_sync(0xffffffffu, tm0, 1));
        tm0 = fmaxf(tm0, __shfl_xor_sync(0xffffffffu, tm0, 2));
        tm1 = fmaxf(tm1, __shfl_xor_sync(0xffffffffu, tm1, 1));
        tm1 = fmaxf(tm1, __shfl_xor_sync(0xffffffffu, tm1, 2));

        float mn0 = fmaxf(mr0, tm0), mn1 = fmaxf(mr1, tm1);
        float corr0 = __expf(mr0 - mn0), corr1 = __expf(mr1 - mn1);
        mr0 = mn0; mr1 = mn1;

        float rs0 = 0.f, rs1 = 0.f;
#pragma unroll
        for (int nf = 0; nf < 8; nf++) {
            float p0 = __expf(s[nf].x - mn0);
            float p1 = __expf(s[nf].y - mn0);
            float p2 = __expf(s[nf].z - mn1);
            float p3 = __expf(s[nf].w - mn1);
            rs0 += p0 + p1;
            rs1 += p2 + p3;
            *(float2*)(Ps + (r0 + g)     * PST + nf * 8 + 2 * c) = make_float2(p0, p1);
            *(float2*)(Ps + (r0 + g + 8) * PST + nf * 8 + 2 * c) = make_float2(p2, p3);
        }
        rs0 += __shfl_xor_sync(0xffffffffu, rs0, 1);
        rs0 += __shfl_xor_sync(0xffffffffu, rs0, 2);
        rs1 += __shfl_xor_sync(0xffffffffu, rs1, 1);
        rs1 += __shfl_xor_sync(0xffffffffu, rs1, 2);
        lr0 = lr0 * corr0 + rs0;
        lr1 = lr1 * corr1 + rs1;
#pragma unroll
        for (int nf = 0; nf < 16; nf++) {
            o[nf].x *= corr0; o[nf].y *= corr0;
            o[nf].z *= corr1; o[nf].w *= corr1;
        }
        __syncwarp();  // Ps stores visible within warp

        // ---- O += P V (16 x 128 per warp), 2xTF32 ----
#pragma unroll 2
        for (int kc = 0; kc < 8; kc++) {
            const int k0 = kc * 8;
            uint32_t ahi[4], alo[4];
            split2(Ps[(r0 + g)     * PST + k0 + c],     ahi[0], alo[0]);
            split2(Ps[(r0 + g + 8) * PST + k0 + c],     ahi[1], alo[1]);
            split2(Ps[(r0 + g)     * PST + k0 + c + 4], ahi[2], alo[2]);
            split2(Ps[(r0 + g + 8) * PST + k0 + c + 4], ahi[3], alo[3]);
#pragma unroll
            for (int nf = 0; nf < 16; nf++) {
                uint32_t bhi[2];
                bhi[0] = uVhi[(k0 + c)     * VST + nf * 8 + g];
                bhi[1] = uVhi[(k0 + c + 4) * VST + nf * 8 + g];
                mma_tf32(o[nf], ahi, bhi);
                mma_tf32(o[nf], alo, bhi);
            }
        }
    }

    // ---- epilogue: normalize, write to g_att ----
    float inv0 = 1.f / lr0, inv1 = 1.f / lr1;
    int t0 = i0 + r0 + g, t1 = t0 + 8;
    float* d0 = g_att + ((size_t)b * TT + t0) * CC + h * DD;
    float* d1 = g_att + ((size_t)b * TT + t1) * CC + h * DD;
#pragma unroll
    for (int nf = 0; nf < 16; nf++) {
        int col = nf * 8 + 2 * c;
        *(float2*)(d0 + col) = make_float2(o[nf].x * inv0, o[nf].y * inv0);
        *(float2*)(d1 + col) = make_float2(o[nf].z * inv1, o[nf].w * inv1);
    }
}

// ---------------------------------------------------------------------------
extern "C" void kernel_launch(void* const* d_in, const int* in_sizes, int n_in,
                              void* d_out, int out_size) {
    (void)in_sizes; (void)n_in; (void)out_size;
    const float* x    = (const float*)d_in[0];
    const float* Wqkv = (const float*)d_in[3];
    const float* Wout = (const float*)d_in[4];
    float* out = (float*)d_out;

    rope_table_kernel<<<TT, 64>>>();

    dim3 g1(3 * CC / 128, BB * TT / 128);   // (48, 32)
    gemm_tf32<0><<<g1, 256>>>(x, Wqkv, nullptr, BB * TT, 3 * CC, CC);

    rope_kernel<<<2 * BB * HH * TT, 64>>>();

    cudaFuncSetAttribute(attn_mma_kernel,
                         cudaFuncAttributeMaxDynamicSharedMemorySize, ATTN_SMEM);
    dim3 g2(TT / AM, BB * HH);              // (16, 32)
    attn_mma_kernel<<<g2, 256, ATTN_SMEM>>>();

    dim3 g3(CC / 128, BB * TT / 128);       // (16, 32)
    gemm_tf32<1><<<g3, 256>>>(nullptr, Wout, out, BB * TT, CC, CC);
}

// round 6
// speedup vs baseline: 3.2118x; 1.2266x over previous
#include <cuda_runtime.h>
#include <math.h>
#include <stdint.h>

#define BB 2
#define TT 2048
#define CC 2048
#define HH 16
#define DD 128
#define NEGF -1000000000.0f

// Scratch (device globals — referenced ONLY from device code)
__device__ float g_qkv[(size_t)3 * BB * HH * TT * DD];  // [3][B][H][T][D]
__device__ float g_klo[(size_t)BB * HH * TT * DD];      // K low part
__device__ float g_att[(size_t)BB * TT * CC];           // [B][T][C] (tf32-rounded)
__device__ float g_xc[(size_t)BB * TT * CC];            // x rounded to tf32
__device__ float g_wqc[(size_t)3 * CC * CC];            // Wqkv rounded
__device__ float g_woc[(size_t)CC * CC];                // Wout rounded
__device__ float g_cos[TT * 64];
__device__ float g_sin[TT * 64];

// ---------------------------------------------------------------------------
__device__ __forceinline__ uint32_t f2tf32(float x) {
    uint32_t r;
    asm volatile("cvt.rna.tf32.f32 %0, %1;\n" : "=r"(r) : "f"(x));
    return r;
}
__device__ __forceinline__ void split2(float x, uint32_t& hi, uint32_t& lo) {
    hi = f2tf32(x);
    lo = f2tf32(x - __uint_as_float(hi));
}
__device__ __forceinline__ void cp_async16(void* smem, const void* gmem) {
    uint32_t s = (uint32_t)__cvta_generic_to_shared(smem);
    asm volatile("cp.async.cg.shared.global [%0], [%1], 16;\n" :: "r"(s), "l"(gmem));
}
__device__ __forceinline__ void mma_tf32(float4& d, const uint32_t a[4], const uint32_t b[2]) {
    asm volatile(
        "mma.sync.aligned.m16n8k8.row.col.f32.tf32.tf32.f32 "
        "{%0,%1,%2,%3}, {%4,%5,%6,%7}, {%8,%9}, {%0,%1,%2,%3};\n"
        : "+f"(d.x), "+f"(d.y), "+f"(d.z), "+f"(d.w)
        : "r"(a[0]), "r"(a[1]), "r"(a[2]), "r"(a[3]), "r"(b[0]), "r"(b[1]));
}

// ---------------------------------------------------------------------------
__global__ void rope_table_kernel() {
    int t = blockIdx.x;
    int d = threadIdx.x;  // 0..63
    double inv = exp2(-((double)(2 * d) / 128.0) * log2(10000.0));
    float f = (float)t * (float)inv;
    g_cos[t * 64 + d] = cosf(f);
    g_sin[t * 64 + d] = sinf(f);
}

// Round an array to tf32-valued fp32 into a device-global destination.
// WHICH: 0 -> g_xc, 1 -> g_wqc, 2 -> g_woc   (dst resolved in DEVICE code)
template <int WHICH>
__global__ void cvt_tf32_kernel(const float* __restrict__ src, int n4) {
    float* dst = (WHICH == 0) ? g_xc : (WHICH == 1) ? g_wqc : g_woc;
    int i = blockIdx.x * blockDim.x + threadIdx.x;
    if (i < n4) {
        float4 v = ((const float4*)src)[i];
        v.x = __uint_as_float(f2tf32(v.x));
        v.y = __uint_as_float(f2tf32(v.y));
        v.z = __uint_as_float(f2tf32(v.z));
        v.w = __uint_as_float(f2tf32(v.w));
        ((float4*)dst)[i] = v;
    }
}

// ---------------------------------------------------------------------------
// RoPE + precision prep:
//   slabs 0..31  (q): rope, round to tf32, in place
//   slabs 32..63 (k): rope, hi in place, lo -> g_klo
//   slabs 64..95 (v): round to tf32, in place
// ---------------------------------------------------------------------------
__global__ void rope_split_kernel() {
    int idx = blockIdx.x;            // [0, 3*B*H*T)
    int t = idx & (TT - 1);
    int s = idx >> 11;               // slab [0, 96)
    float* p = g_qkv + ((size_t)s * TT + t) * DD;
    int d = threadIdx.x;             // 64 threads

    if (s < 2 * BB * HH) {
        float cs = g_cos[t * 64 + d], sn = g_sin[t * 64 + d];
        float x1 = p[d], x2 = p[d + 64];
        float r1 = x1 * cs - x2 * sn;
        float r2 = x2 * cs + x1 * sn;
        if (s < BB * HH) {           // q: hi only
            p[d]      = __uint_as_float(f2tf32(r1));
            p[d + 64] = __uint_as_float(f2tf32(r2));
        } else {                     // k: hi + lo
            uint32_t h1, l1, h2, l2;
            split2(r1, h1, l1);
            split2(r2, h2, l2);
            p[d]      = __uint_as_float(h1);
            p[d + 64] = __uint_as_float(h2);
            float* q = g_klo + ((size_t)(s - BB * HH) * TT + t) * DD;
            q[d]      = __uint_as_float(l1);
            q[d + 64] = __uint_as_float(l2);
        }
    } else {                         // v: round
        p[d]      = __uint_as_float(f2tf32(p[d]));
        p[d + 64] = __uint_as_float(f2tf32(p[d + 64]));
    }
}

// ---------------------------------------------------------------------------
// tf32 mma.sync GEMM (NT), 2-stage cp.async, pre-rounded inputs (no cvt).
// BM=BN=128, BK=32, 256 threads, warps 4(m) x 2(n), each 32x64.
// EPI==0: A=g_xc, W=g_wqc, scatter into g_qkv.
// EPI==1: A=g_att, W=g_woc, plain row-major store to out.
// ---------------------------------------------------------------------------
#define GBK 32
#define STAGE_F (128 * GBK)

__device__ __forceinline__ int sw_off(int row, int k) {
    return row * GBK + ((((k >> 2) ^ (row & 7)) << 2) | (k & 3));
}

template <int EPI>
__global__ void __launch_bounds__(256, 2) gemm_tf32(float* __restrict__ out) {
    __shared__ uint32_t As[2][STAGE_F];
    __shared__ uint32_t Bs[2][STAGE_F];

    const float* A = (EPI == 0) ? (const float*)g_xc  : (const float*)g_att;
    const float* W = (EPI == 0) ? (const float*)g_wqc : (const float*)g_woc;
    const int K = CC;
    const int N = (EPI == 0) ? 3 * CC : CC;

    const int tid = threadIdx.x;
    const int m0 = blockIdx.y * 128, n0 = blockIdx.x * 128;

    const int wid = tid >> 5;
    const int lane = tid & 31;
    const int wm = wid & 3;
    const int wn = wid >> 2;
    const int g = lane >> 2;
    const int c = lane & 3;

    const int lr = tid >> 3;
    const int lc4 = tid & 7;

    float4 acc[2][8];
#pragma unroll
    for (int i = 0; i < 2; i++)
#pragma unroll
        for (int j = 0; j < 8; j++) acc[i][j] = make_float4(0.f, 0.f, 0.f, 0.f);

    const int NT = K / GBK;

    // prologue: stage 0
    {
#pragma unroll
        for (int i = 0; i < 4; i++) {
            int r = lr + i * 32;
            int sw = (lc4 ^ (r & 7)) << 2;
            cp_async16(&As[0][r * GBK + sw], A + (size_t)(m0 + r) * K + lc4 * 4);
            cp_async16(&Bs[0][r * GBK + sw], W + (size_t)(n0 + r) * K + lc4 * 4);
        }
        asm volatile("cp.async.commit_group;\n");
    }

    for (int kt = 0; kt < NT; kt++) {
        int cur = kt & 1;
        if (kt + 1 < NT) {
            int nxt = cur ^ 1;
            int k0 = (kt + 1) * GBK;
#pragma unroll
            for (int i = 0; i < 4; i++) {
                int r = lr + i * 32;
                int sw = (lc4 ^ (r & 7)) << 2;
                cp_async16(&As[nxt][r * GBK + sw], A + (size_t)(m0 + r) * K + k0 + lc4 * 4);
                cp_async16(&Bs[nxt][r * GBK + sw], W + (size_t)(n0 + r) * K + k0 + lc4 * 4);
            }
        }
        asm volatile("cp.async.commit_group;\n");
        asm volatile("cp.async.wait_group 1;\n");
        __syncthreads();

        const uint32_t* as = As[cur];
        const uint32_t* bs = Bs[cur];
#pragma unroll
        for (int ks = 0; ks < 4; ks++) {
            const int k0 = ks * 8;
            uint32_t ua[2][4], ub[8][2];
#pragma unroll
            for (int mf = 0; mf < 2; mf++) {
                int r0 = wm * 32 + mf * 16 + g;
                ua[mf][0] = as[sw_off(r0,     k0 + c)];
                ua[mf][1] = as[sw_off(r0 + 8, k0 + c)];
                ua[mf][2] = as[sw_off(r0,     k0 + c + 4)];
                ua[mf][3] = as[sw_off(r0 + 8, k0 + c + 4)];
            }
#pragma unroll
            for (int nf = 0; nf < 8; nf++) {
                int n = wn * 64 + nf * 8 + g;
                ub[nf][0] = bs[sw_off(n, k0 + c)];
                ub[nf][1] = bs[sw_off(n, k0 + c + 4)];
            }
#pragma unroll
            for (int mf = 0; mf < 2; mf++)
#pragma unroll
                for (int nf = 0; nf < 8; nf++) mma_tf32(acc[mf][nf], ua[mf], ub[nf]);
        }
        __syncthreads();
    }

    if (EPI == 0) {
        const int which = n0 >> 11;
        const int hh = (n0 >> 7) & 15;
#pragma unroll
        for (int mf = 0; mf < 2; mf++) {
            int r0 = m0 + wm * 32 + mf * 16 + g;
            int b0i = r0 >> 11, t0 = r0 & 2047;
            int r1 = r0 + 8;
            int b1i = r1 >> 11, t1 = r1 & 2047;
            float* base0 = g_qkv + ((((size_t)which * BB + b0i) * HH + hh) * TT + t0) * DD;
            float* base1 = g_qkv + ((((size_t)which * BB + b1i) * HH + hh) * TT + t1) * DD;
#pragma unroll
            for (int nf = 0; nf < 8; nf++) {
                int col = wn * 64 + nf * 8 + 2 * c;
                *(float2*)(base0 + col) = make_float2(acc[mf][nf].x, acc[mf][nf].y);
                *(float2*)(base1 + col) = make_float2(acc[mf][nf].z, acc[mf][nf].w);
            }
        }
    } else {
#pragma unroll
        for (int mf = 0; mf < 2; mf++) {
            int r0 = m0 + wm * 32 + mf * 16 + g;
            int r1 = r0 + 8;
#pragma unroll
            for (int nf = 0; nf < 8; nf++) {
                int col = n0 + wn * 64 + nf * 8 + 2 * c;
                *(float2*)(out + (size_t)r0 * N + col) = make_float2(acc[mf][nf].x, acc[mf][nf].y);
                *(float2*)(out + (size_t)r1 * N + col) = make_float2(acc[mf][nf].z, acc[mf][nf].w);
            }
        }
    }
}

// ---------------------------------------------------------------------------
// Flash attention on tensor cores, pre-rounded/pre-split inputs.
// BM=128 q rows, BN=64 keys/iter, 8 warps (16 rows each).
// S = Qhi*(Khi + Klo) (2 passes); PV = (Phi + Plo)*Vhi (2 passes).
// ---------------------------------------------------------------------------
#define AM 128
#define AN 64
#define QST 132
#define KST 132
#define VST 136
#define PST 68

#define OFF_Q   0
#define OFF_KHI (AM * QST)
#define OFF_KLO (OFF_KHI + AN * KST)
#define OFF_VHI (OFF_KLO + AN * KST)
#define OFF_P   (OFF_VHI + AN * VST)
#define ATTN_F  (OFF_P + AM * PST)
#define ATTN_SMEM (ATTN_F * 4)   // 204800 B

__global__ void __launch_bounds__(256) attn_mma_kernel() {
    extern __shared__ float sm[];
    float* Qs  = sm + OFF_Q;
    float* Khi = sm + OFF_KHI;
    float* Klo = sm + OFF_KLO;
    float* Vhi = sm + OFF_VHI;
    float* Ps  = sm + OFF_P;
    const uint32_t* uQs  = (const uint32_t*)Qs;
    const uint32_t* uKhi = (const uint32_t*)Khi;
    const uint32_t* uKlo = (const uint32_t*)Klo;
    const uint32_t* uVhi = (const uint32_t*)Vhi;

    const int bh = blockIdx.y;
    const int b = bh >> 4;
    const int h = bh & 15;
    const int qt = (gridDim.x - 1) - blockIdx.x;   // heavy tiles first
    const int i0 = qt * AM;
    const float slope = (float)exp2(-0.5 * (double)(h + 1));
    const float scale = 0.08838834764831843f;      // 1/sqrt(128)

    const float* Qg  = g_qkv + (size_t)bh * TT * DD;
    const float* Kg  = g_qkv + ((size_t)(BB * HH) + bh) * TT * DD;
    const float* Klg = g_klo + (size_t)bh * TT * DD;
    const float* Vg  = g_qkv + ((size_t)(2 * BB * HH) + bh) * TT * DD;

    const int tid = threadIdx.x;
    const int w = tid >> 5, lane = tid & 31;
    const int g = lane >> 2, c = lane & 3;
    const int r0 = w * 16;

    // Q tile (pre-rounded) via cp.async
    for (int v = tid; v < AM * 32; v += 256) {
        int r = v >> 5, c4 = (v & 31) << 2;
        cp_async16(Qs + r * QST + c4, Qg + (size_t)(i0 + r) * DD + c4);
    }
    asm volatile("cp.async.commit_group;\n");

    float4 o[16];
#pragma unroll
    for (int i = 0; i < 16; i++) o[i] = make_float4(0.f, 0.f, 0.f, 0.f);
    float mr0 = -INFINITY, mr1 = -INFINITY, lr0 = 0.f, lr1 = 0.f;

    const int ntiles = 2 * (qt + 1);
    for (int kt = 0; kt < ntiles; kt++) {
        const int j0 = kt * AN;
        __syncthreads();  // previous PV done before overwriting K/V
        for (int v = tid; v < AN * 32; v += 256) {
            int r = v >> 5, c4 = (v & 31) << 2;
            size_t go = (size_t)(j0 + r) * DD + c4;
            cp_async16(Khi + r * KST + c4, Kg + go);
            cp_async16(Klo + r * KST + c4, Klg + go);
            cp_async16(Vhi + r * VST + c4, Vg + go);
        }
        asm volatile("cp.async.commit_group;\n");
        asm volatile("cp.async.wait_group 0;\n");
        __syncthreads();

        // ---- S = Qhi (Khi + Klo), 16 x 64 per warp ----
        float4 s[8];
#pragma unroll
        for (int nf = 0; nf < 8; nf++) s[nf] = make_float4(0.f, 0.f, 0.f, 0.f);
#pragma unroll 4
        for (int kc = 0; kc < 16; kc++) {
            const int k0 = kc * 8;
            uint32_t ua[4];
            ua[0] = uQs[(r0 + g)     * QST + k0 + c];
            ua[1] = uQs[(r0 + g + 8) * QST + k0 + c];
            ua[2] = uQs[(r0 + g)     * QST + k0 + c + 4];
            ua[3] = uQs[(r0 + g + 8) * QST + k0 + c + 4];
#pragma unroll
            for (int nf = 0; nf < 8; nf++) {
                uint32_t bhi[2], blo[2];
                int nb = (nf * 8 + g) * KST + k0;
                bhi[0] = uKhi[nb + c]; bhi[1] = uKhi[nb + c + 4];
                blo[0] = uKlo[nb + c]; blo[1] = uKlo[nb + c + 4];
                mma_tf32(s[nf], ua, bhi);
                mma_tf32(s[nf], ua, blo);
            }
        }

        // ---- softmax (warp-local rows) ----
        const int ig0 = i0 + r0 + g;
        const int ig1 = ig0 + 8;
        float tm0 = -INFINITY, tm1 = -INFINITY;
#pragma unroll
        for (int nf = 0; nf < 8; nf++) {
            int jb = j0 + nf * 8 + 2 * c;
            s[nf].x = (jb     <= ig0) ? fmaf(slope, (float)(jb     - ig0), s[nf].x * scale) : NEGF;
            s[nf].y = (jb + 1 <= ig0) ? fmaf(slope, (float)(jb + 1 - ig0), s[nf].y * scale) : NEGF;
            s[nf].z = (jb     <= ig1) ? fmaf(slope, (float)(jb     - ig1), s[nf].z * scale) : NEGF;
            s[nf].w = (jb + 1 <= ig1) ? fmaf(slope, (float)(jb + 1 - ig1), s[nf].w * scale) : NEGF;
            tm0 = fmaxf(tm0, fmaxf(s[nf].x, s[nf].y));
            tm1 = fmaxf(tm1, fmaxf(s[nf].z, s[nf].w));
        }
        tm0 = fmaxf(tm0, __shfl_xor_sync(0xffffffffu, tm0, 1));
        tm0 = fmaxf(tm0, __shfl_xor_sync(0xffffffffu, tm0, 2));
        tm1 = fmaxf(tm1, __shfl_xor_sync(0xffffffffu, tm1, 1));
        tm1 = fmaxf(tm1, __shfl_xor_sync(0xffffffffu, tm1, 2));

        float mn0 = fmaxf(mr0, tm0), mn1 = fmaxf(mr1, tm1);
        float corr0 = __expf(mr0 - mn0), corr1 = __expf(mr1 - mn1);
        mr0 = mn0; mr1 = mn1;

        float rs0 = 0.f, rs1 = 0.f;
#pragma unroll
        for (int nf = 0; nf < 8; nf++) {
            float p0 = __expf(s[nf].x - mn0);
            float p1 = __expf(s[nf].y - mn0);
            float p2 = __expf(s[nf].z - mn1);
            float p3 = __expf(s[nf].w - mn1);
            rs0 += p0 + p1;
            rs1 += p2 + p3;
            *(float2*)(Ps + (r0 + g)     * PST + nf * 8 + 2 * c) = make_float2(p0, p1);
            *(float2*)(Ps + (r0 + g + 8) * PST + nf * 8 + 2 * c) = make_float2(p2, p3);
        }
        rs0 += __shfl_xor_sync(0xffffffffu, rs0, 1);
        rs0 += __shfl_xor_sync(0xffffffffu, rs0, 2);
        rs1 += __shfl_xor_sync(0xffffffffu, rs1, 1);
        rs1 += __shfl_xor_sync(0xffffffffu, rs1, 2);
        lr0 = lr0 * corr0 + rs0;
        lr1 = lr1 * corr1 + rs1;
#pragma unroll
        for (int nf = 0; nf < 16; nf++) {
            o[nf].x *= corr0; o[nf].y *= corr0;
            o[nf].z *= corr1; o[nf].w *= corr1;
        }
        __syncwarp();  // Ps visible within warp

        // ---- O += (Phi + Plo) Vhi, 16 x 128 per warp ----
#pragma unroll 2
        for (int kc = 0; kc < 8; kc++) {
            const int k0 = kc * 8;
            uint32_t ahi[4], alo[4];
            split2(Ps[(r0 + g)     * PST + k0 + c],     ahi[0], alo[0]);
            split2(Ps[(r0 + g + 8) * PST + k0 + c],     ahi[1], alo[1]);
            split2(Ps[(r0 + g)     * PST + k0 + c + 4], ahi[2], alo[2]);
            split2(Ps[(r0 + g + 8) * PST + k0 + c + 4], ahi[3], alo[3]);
#pragma unroll
            for (int nf = 0; nf < 16; nf++) {
                uint32_t bhi[2];
                bhi[0] = uVhi[(k0 + c)     * VST + nf * 8 + g];
                bhi[1] = uVhi[(k0 + c + 4) * VST + nf * 8 + g];
                mma_tf32(o[nf], ahi, bhi);
                mma_tf32(o[nf], alo, bhi);
            }
        }
    }

    // ---- epilogue: normalize, round to tf32, write g_att ----
    float inv0 = 1.f / lr0, inv1 = 1.f / lr1;
    int t0 = i0 + r0 + g, t1 = t0 + 8;
    float* d0 = g_att + ((size_t)b * TT + t0) * CC + h * DD;
    float* d1 = g_att + ((size_t)b * TT + t1) * CC + h * DD;
#pragma unroll
    for (int nf = 0; nf < 16; nf++) {
        int col = nf * 8 + 2 * c;
        *(float2*)(d0 + col) = make_float2(__uint_as_float(f2tf32(o[nf].x * inv0)),
                                           __uint_as_float(f2tf32(o[nf].y * inv0)));
        *(float2*)(d1 + col) = make_float2(__uint_as_float(f2tf32(o[nf].z * inv1)),
                                           __uint_as_float(f2tf32(o[nf].w * inv1)));
    }
}

// ---------------------------------------------------------------------------
extern "C" void kernel_launch(void* const* d_in, const int* in_sizes, int n_in,
                              void* d_out, int out_size) {
    (void)in_sizes; (void)n_in; (void)out_size;
    const float* x    = (const float*)d_in[0];
    const float* Wqkv = (const float*)d_in[3];
    const float* Wout = (const float*)d_in[4];
    float* out = (float*)d_out;

    rope_table_kernel<<<TT, 64>>>();

    // pre-round inputs to tf32 (destinations resolved in device code)
    {
        int n4x = BB * TT * CC / 4;
        int n4q = 3 * CC * CC / 4;
        int n4o = CC * CC / 4;
        cvt_tf32_kernel<0><<<(n4x + 255) / 256, 256>>>(x, n4x);
        cvt_tf32_kernel<1><<<(n4q + 255) / 256, 256>>>(Wqkv, n4q);
        cvt_tf32_kernel<2><<<(n4o + 255) / 256, 256>>>(Wout, n4o);
    }

    dim3 g1(3 * CC / 128, BB * TT / 128);   // (48, 32)
    gemm_tf32<0><<<g1, 256>>>(nullptr);

    rope_split_kernel<<<3 * BB * HH * TT, 64>>>();

    cudaFuncSetAttribute(attn_mma_kernel,
                         cudaFuncAttributeMaxDynamicSharedMemorySize, ATTN_SMEM);
    dim3 g2(TT / AM, BB * HH);              // (16, 32)
    attn_mma_kernel<<<g2, 256, ATTN_SMEM>>>();

    dim3 g3(CC / 128, BB * TT / 128);       // (16, 32)
    gemm_tf32<1><<<g3, 256>>>(out);
}